// round 12
// baseline (speedup 1.0000x reference)
#include <cuda_runtime.h>
#include <cuda_bf16.h>
#include <cstdint>

#define B_   64
#define T_   512
#define I_   512
#define H_   512
#define G4   2048
#define NCG  256
#define BG4  (B_ * G4)
#define SEG  64                                          // timesteps per K2 launch

// ------------------------- device scratch ----------------------------------
__device__ uint4    g_WxFrag[32 * 256 * 32];            // [kb][ncf][lane] bf16 frags (Wx)
__device__ uint4    g_WhFrag[64 * 4096];                // [jc][(kb*4+nf)*32+lane] (Wh)
__device__ float    g_bias[G4];
__device__ float    g_xproj[(size_t)T_ * BG4];          // [t][b][n] fp32
__device__ uint32_t g_hHi[2][B_ * 256];                 // [buf][b][k2] bf16x2 hi
__device__ uint32_t g_hLo[2][B_ * 256];                 // [buf][b][k2] bf16x2 lo
__device__ float    g_cs[B_ * H_];                      // cell state between segments
__device__ int      g_count4[4];                        // per-batch-group barrier counters

// ------------------------- helpers -----------------------------------------
__device__ __forceinline__ void bsplit(float v, uint16_t& hi, uint16_t& lo) {
    __nv_bfloat16 h = __float2bfloat16_rn(v);
    float r = v - __bfloat162float(h);
    __nv_bfloat16 l = __float2bfloat16_rn(r);
    hi = __bfloat16_as_ushort(h);
    lo = __bfloat16_as_ushort(l);
}
__device__ __forceinline__ uint32_t bpack(uint16_t e0, uint16_t e1) {
    return (uint32_t)e0 | ((uint32_t)e1 << 16);
}

__device__ __forceinline__ float sigm(float x) { return 1.0f / (1.0f + __expf(-x)); }
__device__ __forceinline__ float tanh_acc(float x) {
    return 1.0f - 2.0f / (__expf(2.0f * x) + 1.0f);
}

__device__ __forceinline__ int ld_acq(const int* p) {
    int v;
    asm volatile("ld.acquire.gpu.global.b32 %0, [%1];" : "=r"(v) : "l"(p) : "memory");
    return v;
}
__device__ __forceinline__ void red_rel(int* p) {
    asm volatile("red.release.gpu.global.add.s32 [%0], %1;" :: "l"(p), "r"(1) : "memory");
}

__device__ __forceinline__ void mma_bf16(float (&d)[4], const uint32_t (&a)[4],
                                         uint32_t b0, uint32_t b1) {
    asm volatile(
        "mma.sync.aligned.m16n8k16.row.col.f32.bf16.bf16.f32 "
        "{%0,%1,%2,%3}, {%4,%5,%6,%7}, {%8,%9}, {%0,%1,%2,%3};"
        : "+f"(d[0]), "+f"(d[1]), "+f"(d[2]), "+f"(d[3])
        : "r"(a[0]), "r"(a[1]), "r"(a[2]), "r"(a[3]), "r"(b0), "r"(b1));
}

__device__ __forceinline__ const float* wsel(int gate, const float* Wf, const float* Wi,
                                             const float* Wo, const float* Wc) {
    return gate == 0 ? Wf : gate == 1 ? Wi : gate == 2 ? Wo : Wc;
}

// ------------------------- K0: pack ----------------------------------------
// Builds Wx frags (round-7 contract) AND Wh frags (verbatim the round-11
// in-kernel builder's index math: k0 = kb*16+2tg, col = jc*8+g, row I_+k).
__global__ void pack_kernel(const float* __restrict__ Wf, const float* __restrict__ Wi,
                            const float* __restrict__ Wo, const float* __restrict__ Wc,
                            const float* __restrict__ bf, const float* __restrict__ bi,
                            const float* __restrict__ bo, const float* __restrict__ bc) {
    int idx = blockIdx.x * blockDim.x + threadIdx.x;
    if (idx < 32 * 256 * 32) {
        int lane = idx & 31, ncf = (idx >> 5) & 255, kb = idx >> 13;
        int g = lane >> 2, tg = lane & 3;
        int k0 = kb * 16 + 2 * tg;
        int col = ncf * 8 + g;
        int gate = col >> 9, j = col & 511;
        const float* W = wsel(gate, Wf, Wi, Wo, Wc);
        float v00 = W[(size_t)k0 * H_ + j];
        float v01 = W[(size_t)(k0 + 1) * H_ + j];
        float v10 = W[(size_t)(k0 + 8) * H_ + j];
        float v11 = W[(size_t)(k0 + 9) * H_ + j];
        uint16_t h00, l00, h01, l01, h10, l10, h11, l11;
        bsplit(v00, h00, l00); bsplit(v01, h01, l01);
        bsplit(v10, h10, l10); bsplit(v11, h11, l11);
        uint4 frag;
        frag.x = bpack(h00, h01);
        frag.y = bpack(h10, h11);
        frag.z = bpack(l00, l01);
        frag.w = bpack(l10, l11);
        g_WxFrag[idx] = frag;
    }
    if (idx < 64 * 4096) {
        // (jc, kb, nf, lane) <- idx;  sWf slot = (kb*4+nf)*32+lane
        int lane = idx & 31, nf = (idx >> 5) & 3, kb = (idx >> 7) & 31, jc = idx >> 12;
        int g = lane >> 2, tg = lane & 3;
        int k0 = kb * 16 + 2 * tg;
        const float* W = wsel(nf, Wf, Wi, Wo, Wc);
        const size_t base = (size_t)(I_ + k0) * H_ + jc * 8 + g;
        float v00 = W[base];
        float v01 = W[base + H_];
        float v10 = W[base + 8 * H_];
        float v11 = W[base + 9 * H_];
        uint16_t h00, l00, h01, l01, h10, l10, h11, l11;
        bsplit(v00, h00, l00); bsplit(v01, h01, l01);
        bsplit(v10, h10, l10); bsplit(v11, h11, l11);
        uint4 frag;
        frag.x = bpack(h00, h01);
        frag.y = bpack(h10, h11);
        frag.z = bpack(l00, l01);
        frag.w = bpack(l10, l11);
        g_WhFrag[(size_t)jc * 4096 + (kb * 4 + nf) * 32 + lane] = frag;
    }
    if (idx < G4) {
        int gate = idx >> 9, j = idx & 511;
        const float* b = gate == 0 ? bf : gate == 1 ? bi : gate == 2 ? bo : bc;
        g_bias[idx] = b[j];
    }
    if (idx < B_ * 256) { g_hHi[0][idx] = 0u; g_hLo[0][idx] = 0u; }
    if (idx < B_ * H_) g_cs[idx] = 0.0f;
    if (idx < 4) g_count4[idx] = 0;
}

// ------------------------- K1: xproj = X @ Wx + bias (3xBF16, frozen) ------
#define K1_SMEM (4 * 4 * 1280 + 2 * 512 * 16)
__global__ void __launch_bounds__(128) xproj_kernel(const float* __restrict__ x) {
    extern __shared__ char sm1raw[];
    uint32_t* sAhi = (uint32_t*)sm1raw;                 // [2][64*20]
    uint32_t* sAlo = sAhi + 2 * 1280;
    uint4*    sBf  = (uint4*)(sm1raw + 4 * 4 * 1280);   // [2][512]

    const int tid = threadIdx.x;
    const int bx = blockIdx.x, by = blockIdx.y;
    const int lane = tid & 31, w = tid >> 5;
    const int g = lane >> 2, tg = lane & 3;
    const int mw = w & 1, nw = w >> 1;

    const int ar = tid >> 3, ac = (tid & 7) * 4;        // A loader
    const float* Abase = x + (size_t)ar * (T_ * I_) + (size_t)by * I_ + ac;

    float4 ra[4];
    uint4  rbf[4];
#pragma unroll
    for (int i = 0; i < 4; i++)
        ra[i] = __ldg((const float4*)(Abase + (size_t)(16 * i) * (T_ * I_)));
#pragma unroll
    for (int i = 0; i < 4; i++) {
        int idx = tid + i * 128;                        // 0..511
        int ln = idx & 31, nf = (idx >> 5) & 7, kbi = idx >> 8;
        rbf[i] = __ldg(&g_WxFrag[((size_t)(0 + kbi) * 256 + bx * 8 + nf) * 32 + ln]);
    }
#pragma unroll
    for (int i = 0; i < 4; i++) {
        uint16_t hx, lx, hy, ly, hz, lz, hw, lw;
        bsplit(ra[i].x, hx, lx); bsplit(ra[i].y, hy, ly);
        bsplit(ra[i].z, hz, lz); bsplit(ra[i].w, hw, lw);
        uint2 vh = {bpack(hx, hy), bpack(hz, hw)};
        uint2 vl = {bpack(lx, ly), bpack(lz, lw)};
        *(uint2*)&sAhi[(ar + 16 * i) * 20 + (ac >> 1)] = vh;
        *(uint2*)&sAlo[(ar + 16 * i) * 20 + (ac >> 1)] = vl;
        sBf[tid + i * 128] = rbf[i];
    }
    __syncthreads();

    float acc[2][4][4] = {};

    for (int kc = 0; kc < 16; kc++) {
        const int cb = kc & 1;
        const int abuf = cb * 1280;
        const int bbuf = cb * 512;
        if (kc < 15) {
#pragma unroll
            for (int i = 0; i < 4; i++)
                ra[i] = __ldg((const float4*)(Abase + (size_t)(16 * i) * (T_ * I_) + (kc + 1) * 32));
#pragma unroll
            for (int i = 0; i < 4; i++) {
                int idx = tid + i * 128;
                int ln = idx & 31, nf = (idx >> 5) & 7, kbi = idx >> 8;
                rbf[i] = __ldg(&g_WxFrag[((size_t)((kc + 1) * 2 + kbi) * 256 + bx * 8 + nf) * 32 + ln]);
            }
        }
#pragma unroll
        for (int kbi = 0; kbi < 2; kbi++) {
            uint32_t ahi[2][4], alo[2][4];
#pragma unroll
            for (int mf = 0; mf < 2; mf++) {
                int r0 = mw * 32 + mf * 16 + g;
                int wa = kbi * 8 + tg;
                ahi[mf][0] = sAhi[abuf + r0 * 20 + wa];
                ahi[mf][1] = sAhi[abuf + (r0 + 8) * 20 + wa];
                ahi[mf][2] = sAhi[abuf + r0 * 20 + wa + 4];
                ahi[mf][3] = sAhi[abuf + (r0 + 8) * 20 + wa + 4];
                alo[mf][0] = sAlo[abuf + r0 * 20 + wa];
                alo[mf][1] = sAlo[abuf + (r0 + 8) * 20 + wa];
                alo[mf][2] = sAlo[abuf + r0 * 20 + wa + 4];
                alo[mf][3] = sAlo[abuf + (r0 + 8) * 20 + wa + 4];
            }
#pragma unroll
            for (int nf = 0; nf < 4; nf++) {
                uint4 wf = sBf[bbuf + (kbi * 8 + nw * 4 + nf) * 32 + lane];
#pragma unroll
                for (int mf = 0; mf < 2; mf++) {
                    mma_bf16(acc[mf][nf], ahi[mf], wf.x, wf.y);
                    mma_bf16(acc[mf][nf], ahi[mf], wf.z, wf.w);
                    mma_bf16(acc[mf][nf], alo[mf], wf.x, wf.y);
                }
            }
        }
        if (kc < 15) {
            const int na = (cb ^ 1) * 1280;
            const int nb = (cb ^ 1) * 512;
            __syncthreads();
#pragma unroll
            for (int i = 0; i < 4; i++) {
                uint16_t hx, lx, hy, ly, hz, lz, hw, lw;
                bsplit(ra[i].x, hx, lx); bsplit(ra[i].y, hy, ly);
                bsplit(ra[i].z, hz, lz); bsplit(ra[i].w, hw, lw);
                uint2 vh = {bpack(hx, hy), bpack(hz, hw)};
                uint2 vl = {bpack(lx, ly), bpack(lz, lw)};
                *(uint2*)&sAhi[na + (ar + 16 * i) * 20 + (ac >> 1)] = vh;
                *(uint2*)&sAlo[na + (ar + 16 * i) * 20 + (ac >> 1)] = vl;
                sBf[nb + tid + i * 128] = rbf[i];
            }
            __syncthreads();
        }
    }

    const size_t outbase = (size_t)by * BG4;
#pragma unroll
    for (int mf = 0; mf < 2; mf++)
#pragma unroll
        for (int nf = 0; nf < 4; nf++) {
            int r = mw * 32 + mf * 16 + g;
            int cg = bx * 64 + nw * 32 + nf * 8 + tg * 2;
            float2 bb = *(const float2*)&g_bias[cg];
            float2 v0 = {acc[mf][nf][0] + bb.x, acc[mf][nf][1] + bb.y};
            float2 v1 = {acc[mf][nf][2] + bb.x, acc[mf][nf][3] + bb.y};
            *(float2*)&g_xproj[outbase + (size_t)r * G4 + cg] = v0;
            *(float2*)&g_xproj[outbase + (size_t)(r + 8) * G4 + cg] = v1;
        }
}

// ------------------------- K2: recurrence segment (3xBF16) ------------------
// 256 CTAs x 128 thr, 2 CTAs/SM. CTA (mb, jc): batch rows [16mb,+16),
// hidden units [8jc,+8) x 4 gates. 4-way k-split; warp 0 reduces + epilogue.
// Runs SEG=64 timesteps per launch; cs spilled to g_cs between segments.
// Wh fragments loaded from pack-built g_WhFrag (64KB coalesced copy).
#define STRA  260
#define SMEM2 (65536 + 2 * 16 * STRA * 4 + 3 * 32 * 4 * 16)

__global__ void __launch_bounds__(128, 2) lstm_kernel(float* __restrict__ out, int t0) {
    extern __shared__ char smemraw[];
    uint4*    sWf  = (uint4*)smemraw;                        // [32 kb][4 nf][32 lane]
    uint32_t* sAh  = (uint32_t*)(smemraw + 65536);           // [16][STRA]
    uint32_t* sAl  = sAh + 16 * STRA;
    float4*   sRed = (float4*)(smemraw + 65536 + 2 * 16 * STRA * 4);  // [3*32][4]

    const int tid = threadIdx.x;
    const int bxid = blockIdx.x;
    const int mb = bxid >> 6, jc = bxid & 63;
    const int lane = tid & 31, w = tid >> 5;
    const int g = lane >> 2, tg = lane & 3;
    const int j0 = jc * 8 + tg * 2;

    // ---- load Wh fragments (straight copy; layout contract from pack) ----
    {
        const uint4* src = g_WhFrag + (size_t)jc * 4096;
        for (int i = tid; i < 4096; i += 128) sWf[i] = src[i];
    }
    __syncthreads();

    // ---- cell state + xproj prefetch (warp 0) ----
    float cs[4] = {0.0f, 0.0f, 0.0f, 0.0f};
    float2 xp[8];
    if (w == 0) {
#pragma unroll
        for (int rr = 0; rr < 2; rr++) {
            int b = mb * 16 + g + rr * 8;
            float2 c2 = *(const float2*)&g_cs[(size_t)b * H_ + j0];
            cs[rr * 2 + 0] = c2.x;
            cs[rr * 2 + 1] = c2.y;
        }
#pragma unroll
        for (int gate = 0; gate < 4; gate++)
#pragma unroll
            for (int rr = 0; rr < 2; rr++) {
                int b = mb * 16 + g + rr * 8;
                xp[gate * 2 + rr] = __ldg((const float2*)(
                    g_xproj + (size_t)t0 * BG4 + (size_t)b * G4 + gate * 512 + j0));
            }
    }

    for (int t = t0; t < t0 + SEG; t++) {
        // ---- copy this group's 16 h rows (hi+lo) into smem ----
        const uint32_t* hsH = g_hHi[t & 1];
        const uint32_t* hsL = g_hLo[t & 1];
#pragma unroll
        for (int i = 0; i < 8; i++) {
            int idx = tid + i * 128;           // 0..1023 uint4 slots
            int r = idx >> 6, c4 = (idx & 63) * 4;
            uint4 vh = __ldcg((const uint4*)(hsH + (mb * 16 + r) * 256 + c4));
            uint4 vl = __ldcg((const uint4*)(hsL + (mb * 16 + r) * 256 + c4));
            *(uint4*)&sAh[r * STRA + c4] = vh;
            *(uint4*)&sAl[r * STRA + c4] = vl;
        }
        __syncthreads();

        // ---- GEMM: warp w covers kb = 8w..8w+7 (4-way k-split) ----
        float acc1[4][4] = {}, acc2[4][4] = {}, acc3[4][4] = {};
#pragma unroll
        for (int kbi = 0; kbi < 8; kbi++) {
            const int kb = w * 8 + kbi;
            const int wa = kb * 8 + tg;
            uint32_t ahi[4], alo[4];
            ahi[0] = sAh[g * STRA + wa];
            ahi[1] = sAh[(g + 8) * STRA + wa];
            ahi[2] = sAh[g * STRA + wa + 4];
            ahi[3] = sAh[(g + 8) * STRA + wa + 4];
            alo[0] = sAl[g * STRA + wa];
            alo[1] = sAl[(g + 8) * STRA + wa];
            alo[2] = sAl[g * STRA + wa + 4];
            alo[3] = sAl[(g + 8) * STRA + wa + 4];
            const uint4* wfb = sWf + (kb * 4) * 32 + lane;
#pragma unroll
            for (int nf = 0; nf < 4; nf++) {
                uint4 wf = wfb[nf * 32];
                mma_bf16(acc1[nf], ahi, wf.x, wf.y);
                mma_bf16(acc2[nf], ahi, wf.z, wf.w);
                mma_bf16(acc3[nf], alo, wf.x, wf.y);
            }
        }

        // ---- k-reduce: warps 1-3 publish, warp 0 sums + epilogue ----
        if (w > 0) {
#pragma unroll
            for (int nf = 0; nf < 4; nf++)
                sRed[((w - 1) * 32 + lane) * 4 + nf] = make_float4(
                    acc1[nf][0] + acc2[nf][0] + acc3[nf][0],
                    acc1[nf][1] + acc2[nf][1] + acc3[nf][1],
                    acc1[nf][2] + acc2[nf][2] + acc3[nf][2],
                    acc1[nf][3] + acc2[nf][3] + acc3[nf][3]);
        }
        __syncthreads();

        float hout[4];
        if (w == 0) {
            float acc[4][4];
#pragma unroll
            for (int nf = 0; nf < 4; nf++)
#pragma unroll
                for (int q = 0; q < 4; q++)
                    acc[nf][q] = acc1[nf][q] + acc2[nf][q] + acc3[nf][q];
#pragma unroll
            for (int s = 0; s < 3; s++)
#pragma unroll
                for (int nf = 0; nf < 4; nf++) {
                    float4 r4 = sRed[(s * 32 + lane) * 4 + nf];
                    acc[nf][0] += r4.x; acc[nf][1] += r4.y;
                    acc[nf][2] += r4.z; acc[nf][3] += r4.w;
                }

            // ---- epilogue: gates + state update ----
#pragma unroll
            for (int rr = 0; rr < 2; rr++) {
#pragma unroll
                for (int p = 0; p < 2; p++) {
                    int q = rr * 2 + p;
                    float xf = p == 0 ? xp[0 + rr].x : xp[0 + rr].y;
                    float xi = p == 0 ? xp[2 + rr].x : xp[2 + rr].y;
                    float xo = p == 0 ? xp[4 + rr].x : xp[4 + rr].y;
                    float xc = p == 0 ? xp[6 + rr].x : xp[6 + rr].y;
                    float fg = sigm(acc[0][q] + xf);
                    float ig = sigm(acc[1][q] + xi);
                    float og = sigm(acc[2][q] + xo);
                    float Cg = tanh_acc(acc[3][q] + xc);
                    cs[q] = fg * cs[q] + ig * Cg;
                    hout[q] = og * tanh_acc(cs[q]);
                }
            }

            if (t == T_ - 1) {
#pragma unroll
                for (int rr = 0; rr < 2; rr++) {
                    int b = mb * 16 + g + rr * 8;
                    float2 v = {hout[rr * 2 + 0], hout[rr * 2 + 1]};
                    *(float2*)&out[(size_t)b * H_ + j0] = v;
                }
            } else {
                uint32_t* dH = g_hHi[(t + 1) & 1];
                uint32_t* dL = g_hLo[(t + 1) & 1];
#pragma unroll
                for (int rr = 0; rr < 2; rr++) {
                    int b = mb * 16 + g + rr * 8;
                    uint16_t h0h, h0l, h1h, h1l;
                    bsplit(hout[rr * 2 + 0], h0h, h0l);
                    bsplit(hout[rr * 2 + 1], h1h, h1l);
                    __stcg(&dH[b * 256 + jc * 4 + tg], bpack(h0h, h1h));
                    __stcg(&dL[b * 256 + jc * 4 + tg], bpack(h0l, h1l));
                }
            }
        }
        if (t == T_ - 1) break;

        // ---- group barrier (64 arrivals), xp prefetch in its shadow ----
        __syncthreads();                          // h stores ordered before arrive
        if (tid == 0) red_rel(&g_count4[mb]);     // release arrival

        if (w == 0) {                             // prefetch xproj for t+1
            const float* xsrc = g_xproj + (size_t)(t + 1) * BG4;
#pragma unroll
            for (int gate = 0; gate < 4; gate++)
#pragma unroll
                for (int rr = 0; rr < 2; rr++) {
                    int b = mb * 16 + g + rr * 8;
                    xp[gate * 2 + rr] =
                        __ldg((const float2*)(xsrc + (size_t)b * G4 + gate * 512 + j0));
                }
        }

        if (tid == 0) {
            while (ld_acq(&g_count4[mb]) < 64 * (t + 1)) {}
        }
        __syncthreads();
    }

    // ---- spill cell state for the next segment ----
    if (w == 0) {
#pragma unroll
        for (int rr = 0; rr < 2; rr++) {
            int b = mb * 16 + g + rr * 8;
            float2 c2 = {cs[rr * 2 + 0], cs[rr * 2 + 1]};
            *(float2*)&g_cs[(size_t)b * H_ + j0] = c2;
        }
    }
}

// ------------------------- launch ------------------------------------------
extern "C" void kernel_launch(void* const* d_in, const int* in_sizes, int n_in,
                              void* d_out, int out_size) {
    (void)in_sizes; (void)n_in; (void)out_size;
    const float* x  = (const float*)d_in[0];
    const float* Wf = (const float*)d_in[1];
    const float* bf = (const float*)d_in[2];
    const float* Wi = (const float*)d_in[3];
    const float* bi = (const float*)d_in[4];
    const float* Wo = (const float*)d_in[5];
    const float* bo = (const float*)d_in[6];
    const float* Wc = (const float*)d_in[7];
    const float* bc = (const float*)d_in[8];

    cudaFuncSetAttribute(xproj_kernel, cudaFuncAttributeMaxDynamicSharedMemorySize, K1_SMEM);
    cudaFuncSetAttribute(lstm_kernel, cudaFuncAttributeMaxDynamicSharedMemorySize, SMEM2);

    pack_kernel<<<4096, 256>>>(Wf, Wi, Wo, Wc, bf, bi, bo, bc);
    dim3 gx(32, 512);
    xproj_kernel<<<gx, 128, K1_SMEM>>>(x);
    for (int s = 0; s < 8; s++)
        lstm_kernel<<<NCG, 128, SMEM2>>>((float*)d_out, s * SEG);
}

// round 13
// speedup vs baseline: 1.1444x; 1.1444x over previous
#include <cuda_runtime.h>
#include <cuda_bf16.h>
#include <cstdint>

#define B_   64
#define T_   512
#define I_   512
#define H_   512
#define G4   2048
#define NCG  256
#define BG4  (B_ * G4)
#define SEG  64                                          // timesteps per K2 launch

// ------------------------- device scratch ----------------------------------
__device__ uint4    g_WxFrag[32 * 256 * 32];            // [kb][ncf][lane] bf16 frags (Wx)
__device__ uint4    g_WhFrag[64 * 4096];                // [jc][(kb*4+nf)*32+lane] (Wh)
__device__ float    g_bias[G4];
__device__ float    g_xproj[(size_t)T_ * BG4];          // [t][b][n] fp32
__device__ uint2    g_hP[2][B_ * 256];                  // [buf][b][k2] {hi-pair, lo-pair}
__device__ float    g_cs[B_ * H_];                      // cell state between segments
__device__ int      g_count4[4];                        // per-batch-group barrier counters

// ------------------------- helpers -----------------------------------------
__device__ __forceinline__ void bsplit(float v, uint16_t& hi, uint16_t& lo) {
    __nv_bfloat16 h = __float2bfloat16_rn(v);
    float r = v - __bfloat162float(h);
    __nv_bfloat16 l = __float2bfloat16_rn(r);
    hi = __bfloat16_as_ushort(h);
    lo = __bfloat16_as_ushort(l);
}
__device__ __forceinline__ uint32_t bpack(uint16_t e0, uint16_t e1) {
    return (uint32_t)e0 | ((uint32_t)e1 << 16);
}

__device__ __forceinline__ float sigm(float x) { return 1.0f / (1.0f + __expf(-x)); }
__device__ __forceinline__ float tanh_acc(float x) {
    return 1.0f - 2.0f / (__expf(2.0f * x) + 1.0f);
}

__device__ __forceinline__ int ld_acq(const int* p) {
    int v;
    asm volatile("ld.acquire.gpu.global.b32 %0, [%1];" : "=r"(v) : "l"(p) : "memory");
    return v;
}
__device__ __forceinline__ void red_rel(int* p) {
    asm volatile("red.release.gpu.global.add.s32 [%0], %1;" :: "l"(p), "r"(1) : "memory");
}

__device__ __forceinline__ void mma_bf16(float (&d)[4], const uint32_t (&a)[4],
                                         uint32_t b0, uint32_t b1) {
    asm volatile(
        "mma.sync.aligned.m16n8k16.row.col.f32.bf16.bf16.f32 "
        "{%0,%1,%2,%3}, {%4,%5,%6,%7}, {%8,%9}, {%0,%1,%2,%3};"
        : "+f"(d[0]), "+f"(d[1]), "+f"(d[2]), "+f"(d[3])
        : "r"(a[0]), "r"(a[1]), "r"(a[2]), "r"(a[3]), "r"(b0), "r"(b1));
}

__device__ __forceinline__ const float* wsel(int gate, const float* Wf, const float* Wi,
                                             const float* Wo, const float* Wc) {
    return gate == 0 ? Wf : gate == 1 ? Wi : gate == 2 ? Wo : Wc;
}

// ------------------------- K0: pack (frozen contracts) ----------------------
__global__ void pack_kernel(const float* __restrict__ Wf, const float* __restrict__ Wi,
                            const float* __restrict__ Wo, const float* __restrict__ Wc,
                            const float* __restrict__ bf, const float* __restrict__ bi,
                            const float* __restrict__ bo, const float* __restrict__ bc) {
    int idx = blockIdx.x * blockDim.x + threadIdx.x;
    if (idx < 32 * 256 * 32) {
        int lane = idx & 31, ncf = (idx >> 5) & 255, kb = idx >> 13;
        int g = lane >> 2, tg = lane & 3;
        int k0 = kb * 16 + 2 * tg;
        int col = ncf * 8 + g;
        int gate = col >> 9, j = col & 511;
        const float* W = wsel(gate, Wf, Wi, Wo, Wc);
        float v00 = W[(size_t)k0 * H_ + j];
        float v01 = W[(size_t)(k0 + 1) * H_ + j];
        float v10 = W[(size_t)(k0 + 8) * H_ + j];
        float v11 = W[(size_t)(k0 + 9) * H_ + j];
        uint16_t h00, l00, h01, l01, h10, l10, h11, l11;
        bsplit(v00, h00, l00); bsplit(v01, h01, l01);
        bsplit(v10, h10, l10); bsplit(v11, h11, l11);
        uint4 frag;
        frag.x = bpack(h00, h01);
        frag.y = bpack(h10, h11);
        frag.z = bpack(l00, l01);
        frag.w = bpack(l10, l11);
        g_WxFrag[idx] = frag;
    }
    if (idx < 64 * 4096) {
        int lane = idx & 31, nf = (idx >> 5) & 3, kb = (idx >> 7) & 31, jc = idx >> 12;
        int g = lane >> 2, tg = lane & 3;
        int k0 = kb * 16 + 2 * tg;
        const float* W = wsel(nf, Wf, Wi, Wo, Wc);
        const size_t base = (size_t)(I_ + k0) * H_ + jc * 8 + g;
        float v00 = W[base];
        float v01 = W[base + H_];
        float v10 = W[base + 8 * H_];
        float v11 = W[base + 9 * H_];
        uint16_t h00, l00, h01, l01, h10, l10, h11, l11;
        bsplit(v00, h00, l00); bsplit(v01, h01, l01);
        bsplit(v10, h10, l10); bsplit(v11, h11, l11);
        uint4 frag;
        frag.x = bpack(h00, h01);
        frag.y = bpack(h10, h11);
        frag.z = bpack(l00, l01);
        frag.w = bpack(l10, l11);
        g_WhFrag[(size_t)jc * 4096 + (kb * 4 + nf) * 32 + lane] = frag;
    }
    if (idx < G4) {
        int gate = idx >> 9, j = idx & 511;
        const float* b = gate == 0 ? bf : gate == 1 ? bi : gate == 2 ? bo : bc;
        g_bias[idx] = b[j];
    }
    if (idx < B_ * 256) g_hP[0][idx] = make_uint2(0u, 0u);   // h_0 = 0
    if (idx < B_ * H_) g_cs[idx] = 0.0f;
    if (idx < 4) g_count4[idx] = 0;
}

// ------------------------- K1: xproj = X @ Wx + bias (3xBF16, frozen) ------
#define K1_SMEM (4 * 4 * 1280 + 2 * 512 * 16)
__global__ void __launch_bounds__(128) xproj_kernel(const float* __restrict__ x) {
    extern __shared__ char sm1raw[];
    uint32_t* sAhi = (uint32_t*)sm1raw;                 // [2][64*20]
    uint32_t* sAlo = sAhi + 2 * 1280;
    uint4*    sBf  = (uint4*)(sm1raw + 4 * 4 * 1280);   // [2][512]

    const int tid = threadIdx.x;
    const int bx = blockIdx.x, by = blockIdx.y;
    const int lane = tid & 31, w = tid >> 5;
    const int g = lane >> 2, tg = lane & 3;
    const int mw = w & 1, nw = w >> 1;

    const int ar = tid >> 3, ac = (tid & 7) * 4;        // A loader
    const float* Abase = x + (size_t)ar * (T_ * I_) + (size_t)by * I_ + ac;

    float4 ra[4];
    uint4  rbf[4];
#pragma unroll
    for (int i = 0; i < 4; i++)
        ra[i] = __ldg((const float4*)(Abase + (size_t)(16 * i) * (T_ * I_)));
#pragma unroll
    for (int i = 0; i < 4; i++) {
        int idx = tid + i * 128;                        // 0..511
        int ln = idx & 31, nf = (idx >> 5) & 7, kbi = idx >> 8;
        rbf[i] = __ldg(&g_WxFrag[((size_t)(0 + kbi) * 256 + bx * 8 + nf) * 32 + ln]);
    }
#pragma unroll
    for (int i = 0; i < 4; i++) {
        uint16_t hx, lx, hy, ly, hz, lz, hw, lw;
        bsplit(ra[i].x, hx, lx); bsplit(ra[i].y, hy, ly);
        bsplit(ra[i].z, hz, lz); bsplit(ra[i].w, hw, lw);
        uint2 vh = {bpack(hx, hy), bpack(hz, hw)};
        uint2 vl = {bpack(lx, ly), bpack(lz, lw)};
        *(uint2*)&sAhi[(ar + 16 * i) * 20 + (ac >> 1)] = vh;
        *(uint2*)&sAlo[(ar + 16 * i) * 20 + (ac >> 1)] = vl;
        sBf[tid + i * 128] = rbf[i];
    }
    __syncthreads();

    float acc[2][4][4] = {};

    for (int kc = 0; kc < 16; kc++) {
        const int cb = kc & 1;
        const int abuf = cb * 1280;
        const int bbuf = cb * 512;
        if (kc < 15) {
#pragma unroll
            for (int i = 0; i < 4; i++)
                ra[i] = __ldg((const float4*)(Abase + (size_t)(16 * i) * (T_ * I_) + (kc + 1) * 32));
#pragma unroll
            for (int i = 0; i < 4; i++) {
                int idx = tid + i * 128;
                int ln = idx & 31, nf = (idx >> 5) & 7, kbi = idx >> 8;
                rbf[i] = __ldg(&g_WxFrag[((size_t)((kc + 1) * 2 + kbi) * 256 + bx * 8 + nf) * 32 + ln]);
            }
        }
#pragma unroll
        for (int kbi = 0; kbi < 2; kbi++) {
            uint32_t ahi[2][4], alo[2][4];
#pragma unroll
            for (int mf = 0; mf < 2; mf++) {
                int r0 = mw * 32 + mf * 16 + g;
                int wa = kbi * 8 + tg;
                ahi[mf][0] = sAhi[abuf + r0 * 20 + wa];
                ahi[mf][1] = sAhi[abuf + (r0 + 8) * 20 + wa];
                ahi[mf][2] = sAhi[abuf + r0 * 20 + wa + 4];
                ahi[mf][3] = sAhi[abuf + (r0 + 8) * 20 + wa + 4];
                alo[mf][0] = sAlo[abuf + r0 * 20 + wa];
                alo[mf][1] = sAlo[abuf + (r0 + 8) * 20 + wa];
                alo[mf][2] = sAlo[abuf + r0 * 20 + wa + 4];
                alo[mf][3] = sAlo[abuf + (r0 + 8) * 20 + wa + 4];
            }
#pragma unroll
            for (int nf = 0; nf < 4; nf++) {
                uint4 wf = sBf[bbuf + (kbi * 8 + nw * 4 + nf) * 32 + lane];
#pragma unroll
                for (int mf = 0; mf < 2; mf++) {
                    mma_bf16(acc[mf][nf], ahi[mf], wf.x, wf.y);
                    mma_bf16(acc[mf][nf], ahi[mf], wf.z, wf.w);
                    mma_bf16(acc[mf][nf], alo[mf], wf.x, wf.y);
                }
            }
        }
        if (kc < 15) {
            const int na = (cb ^ 1) * 1280;
            const int nb = (cb ^ 1) * 512;
            __syncthreads();
#pragma unroll
            for (int i = 0; i < 4; i++) {
                uint16_t hx, lx, hy, ly, hz, lz, hw, lw;
                bsplit(ra[i].x, hx, lx); bsplit(ra[i].y, hy, ly);
                bsplit(ra[i].z, hz, lz); bsplit(ra[i].w, hw, lw);
                uint2 vh = {bpack(hx, hy), bpack(hz, hw)};
                uint2 vl = {bpack(lx, ly), bpack(lz, lw)};
                *(uint2*)&sAhi[na + (ar + 16 * i) * 20 + (ac >> 1)] = vh;
                *(uint2*)&sAlo[na + (ar + 16 * i) * 20 + (ac >> 1)] = vl;
                sBf[nb + tid + i * 128] = rbf[i];
            }
            __syncthreads();
        }
    }

    const size_t outbase = (size_t)by * BG4;
#pragma unroll
    for (int mf = 0; mf < 2; mf++)
#pragma unroll
        for (int nf = 0; nf < 4; nf++) {
            int r = mw * 32 + mf * 16 + g;
            int cg = bx * 64 + nw * 32 + nf * 8 + tg * 2;
            float2 bb = *(const float2*)&g_bias[cg];
            float2 v0 = {acc[mf][nf][0] + bb.x, acc[mf][nf][1] + bb.y};
            float2 v1 = {acc[mf][nf][2] + bb.x, acc[mf][nf][3] + bb.y};
            *(float2*)&g_xproj[outbase + (size_t)r * G4 + cg] = v0;
            *(float2*)&g_xproj[outbase + (size_t)(r + 8) * G4 + cg] = v1;
        }
}

// ------------------------- K2: recurrence segment (3xBF16, direct-LDG) ------
// 256 CTAs x 128 thr. CTA (mb, jc): batch rows [16mb,+16), hidden [8jc,+8).
// A fragments loaded DIRECTLY from g_hP (no smem staging). 4-way k-split;
// partials in sP; ALL 128 threads do one (b,j) element's epilogue each.
#define SMEM2 (65536 + 8192)

__global__ void __launch_bounds__(128, 2) lstm_kernel(float* __restrict__ out, int t0) {
    extern __shared__ char smemraw[];
    uint4* sWf = (uint4*)smemraw;                 // [32 kb][4 nf][32 lane]
    float* sP  = (float*)(smemraw + 65536);       // [4 w][4 nf][16 b][8 j]

    const int tid = threadIdx.x;
    const int bxid = blockIdx.x;
    const int mb = bxid >> 6, jc = bxid & 63;
    const int lane = tid & 31, w = tid >> 5;
    const int g = lane >> 2, tg = lane & 3;
    const int bloc = tid >> 3, jloc = tid & 7;    // epilogue element (b, j)
    const int bglob = mb * 16 + bloc;
    const int jglob = jc * 8 + jloc;
    const int rowbase = mb * 16;

    // ---- load Wh fragments (layout contract from pack) ----
    {
        const uint4* src = g_WhFrag + (size_t)jc * 4096;
        for (int i = tid; i < 4096; i += 128) sWf[i] = src[i];
    }
    __syncthreads();

    // ---- per-thread state: one (b,j) element ----
    float cs = g_cs[(size_t)bglob * H_ + jglob];
    float xp[4];
#pragma unroll
    for (int gate = 0; gate < 4; gate++)
        xp[gate] = __ldg(&g_xproj[(size_t)t0 * BG4 + (size_t)bglob * G4 + gate * 512 + jglob]);

    for (int t = t0; t < t0 + SEG; t++) {
        // ---- GEMM: A fragments direct from global (one L2 RT, 32 LDG.64) ----
        const uint2* hp = g_hP[t & 1];
        float acc1[4][4] = {}, acc2[4][4] = {}, acc3[4][4] = {};
#pragma unroll
        for (int kbi = 0; kbi < 8; kbi++) {
            const int kb = w * 8 + kbi;
            const int wa = kb * 8 + tg;
            uint2 v0 = __ldcg(&hp[(rowbase + g) * 256 + wa]);
            uint2 v1 = __ldcg(&hp[(rowbase + g + 8) * 256 + wa]);
            uint2 v2 = __ldcg(&hp[(rowbase + g) * 256 + wa + 4]);
            uint2 v3 = __ldcg(&hp[(rowbase + g + 8) * 256 + wa + 4]);
            uint32_t ahi[4] = {v0.x, v1.x, v2.x, v3.x};
            uint32_t alo[4] = {v0.y, v1.y, v2.y, v3.y};
            const uint4* wfb = sWf + (kb * 4) * 32 + lane;
#pragma unroll
            for (int nf = 0; nf < 4; nf++) {
                uint4 wf = wfb[nf * 32];
                mma_bf16(acc1[nf], ahi, wf.x, wf.y);
                mma_bf16(acc2[nf], ahi, wf.z, wf.w);
                mma_bf16(acc3[nf], alo, wf.x, wf.y);
            }
        }

        // ---- publish partials: (lane g,tg; q) -> element (b, j) ----
#pragma unroll
        for (int nf = 0; nf < 4; nf++)
#pragma unroll
            for (int q = 0; q < 4; q++) {
                int bq = g + 8 * (q >> 1), jq = tg * 2 + (q & 1);
                sP[((w * 4 + nf) * 16 + bq) * 8 + jq] =
                    acc1[nf][q] + acc2[nf][q] + acc3[nf][q];
            }
        __syncthreads();

        // ---- distributed epilogue: each thread reduces + updates 1 element ----
        float a4[4];
#pragma unroll
        for (int nf = 0; nf < 4; nf++) {
            float s = xp[nf];
#pragma unroll
            for (int ww = 0; ww < 4; ww++)
                s += sP[((ww * 4 + nf) * 16 + bloc) * 8 + jloc];
            a4[nf] = s;
        }
        float fg = sigm(a4[0]);
        float ig = sigm(a4[1]);
        float og = sigm(a4[2]);
        float Cg = tanh_acc(a4[3]);
        cs = fg * cs + ig * Cg;
        float hout = og * tanh_acc(cs);

        if (t == T_ - 1) {
            out[(size_t)bglob * H_ + jglob] = hout;
            break;
        }

        // ---- write h_{t+1}: pair via shfl, even lanes store 8B ----
        uint16_t hh, hl;
        bsplit(hout, hh, hl);
        uint32_t mine = bpack(hh, hl);
        uint32_t other = __shfl_xor_sync(0xFFFFFFFF, mine, 1);
        if ((jloc & 1) == 0) {
            uint32_t hiw = (mine & 0xFFFFu) | (other << 16);
            uint32_t low = (mine >> 16) | (other & 0xFFFF0000u);
            __stcg((uint2*)&g_hP[(t + 1) & 1][bglob * 256 + jc * 4 + (jloc >> 1)],
                   make_uint2(hiw, low));
        }
        __syncthreads();                          // h stores ordered before arrive
        if (tid == 0) red_rel(&g_count4[mb]);     // release arrival

        // xproj prefetch for t+1 in the barrier's shadow
#pragma unroll
        for (int gate = 0; gate < 4; gate++)
            xp[gate] = __ldg(&g_xproj[(size_t)(t + 1) * BG4 +
                                      (size_t)bglob * G4 + gate * 512 + jglob]);

        if (tid == 0) {
            while (ld_acq(&g_count4[mb]) < 64 * (t + 1)) {}
        }
        __syncthreads();
    }

    // ---- spill cell state for the next segment ----
    g_cs[(size_t)bglob * H_ + jglob] = cs;
}

// ------------------------- launch ------------------------------------------
extern "C" void kernel_launch(void* const* d_in, const int* in_sizes, int n_in,
                              void* d_out, int out_size) {
    (void)in_sizes; (void)n_in; (void)out_size;
    const float* x  = (const float*)d_in[0];
    const float* Wf = (const float*)d_in[1];
    const float* bf = (const float*)d_in[2];
    const float* Wi = (const float*)d_in[3];
    const float* bi = (const float*)d_in[4];
    const float* Wo = (const float*)d_in[5];
    const float* bo = (const float*)d_in[6];
    const float* Wc = (const float*)d_in[7];
    const float* bc = (const float*)d_in[8];

    cudaFuncSetAttribute(xproj_kernel, cudaFuncAttributeMaxDynamicSharedMemorySize, K1_SMEM);
    cudaFuncSetAttribute(lstm_kernel, cudaFuncAttributeMaxDynamicSharedMemorySize, SMEM2);

    pack_kernel<<<4096, 256>>>(Wf, Wi, Wo, Wc, bf, bi, bo, bc);
    dim3 gx(32, 512);
    xproj_kernel<<<gx, 128, K1_SMEM>>>(x);
    for (int s = 0; s < 8; s++)
        lstm_kernel<<<NCG, 128, SMEM2>>>((float*)d_out, s * SEG);
}